// round 14
// baseline (speedup 1.0000x reference)
#include <cuda_runtime.h>
#include <cuda_fp16.h>
#include <cstdint>

// ROIAlign(7x7, sr=2) + global avg pool via separable weights + HMMA.
//
// out[roi,ch] = sum_{r,c} a[roi][r]*b[roi][c] * F[bi,ch,r,c]
// Per (batch, 16-row strip, 16-channel block):
//   D[48 rois x 16 ch] += A[48 x K] * B[K x 16],  K = 16*128 dense,
// via mma.sync.m16n8k16 (fp16 in, fp32 acc), 3 roi-groups x 2 channel
// halves. Weight fragments A = half(a[roi][r]) * half(b[roi][c]) are built
// once per kstep and reused for BOTH channel halves (the v1 bottleneck was
// rebuilding them per 8-channel block across 32 blocks).

#define C_CH   256
#define HWD    128
#define RS     16
#define CB     16
#define NTHREADS 256
#define SLAB_H  (RS * HWD + 8)   // halves per channel slab (16B pad)
#define SB_STR  136              // sb row stride in halves
#define SA_STR  18               // sa row stride in halves
#define PASS    48               // rois per pass (3 mma groups of 16)
#define MAXL    192

// dynamic smem layout (bytes)
#define OFF_TILE 0
#define OFF_SB   (OFF_TILE + CB * SLAB_H * 2)        // 65792
#define OFF_SA   (OFF_SB + PASS * SB_STR * 2)        // +13056
#define OFF_ACC  (OFF_SA + PASS * SA_STR * 2)        // +1728
#define OFF_LIST (OFF_ACC + PASS * CB * 4)           // +3072
#define OFF_CNT  (OFF_LIST + MAXL * 2)               // +384
#define SMEM_TOTAL (OFF_CNT + 16)

__device__ __align__(16) float g_a[512 * 128];
__device__ __align__(16) float g_b[512 * 192];
__device__ int4 g_meta[512];     // {bi, rlo, rhi, nch8<<8 | base8}

// ---------------------------------------------------------------------------
// Setup: one 32-thread block per ROI (marginals + meta + out init).
// ---------------------------------------------------------------------------
__global__ void roi_setup_kernel(const float* __restrict__ rois,
                                 float* __restrict__ out, int n_rois)
{
    __shared__ float sa[128];
    __shared__ float sb[192];
    __shared__ int rlo_s, rhi_s, clo_s, chi_s;

    const int roi  = blockIdx.x;
    const int lane = threadIdx.x;

    if (lane == 0) { rlo_s = 1 << 30; rhi_s = -1; clo_s = 1 << 30; chi_s = -1; }
    for (int i = lane; i < 192; i += 32) { if (i < 128) sa[i] = 0.f; sb[i] = 0.f; }
    __syncwarp();

    const bool isY = (lane < 14);
    const bool isX = (lane >= 16 && lane < 30);
    if (isY || isX) {
        const int s = isY ? lane : lane - 16;
        const float cx = rois[roi * 6 + 2];
        const float cy = rois[roi * 6 + 3];
        const float w  = rois[roi * 6 + 4];
        const float h  = rois[roi * 6 + 5];
        // Reference rounds the scaled corners through fp16.
        const float x1 = __half2float(__float2half_rn((cx - 0.5f * w) * 128.f));
        const float x2 = __half2float(__float2half_rn((cx + 0.5f * w) * 128.f));
        const float y1 = __half2float(__float2half_rn((cy - 0.5f * h) * 128.f));
        const float y2 = __half2float(__float2half_rn((cy + 0.5f * h) * 128.f));
        const float rw = fmaxf(x2 - x1, 1.f);
        const float rh = fmaxf(y2 - y1, 1.f);

        const float off   = 0.25f + 0.5f * (float)s;
        const float start = isY ? y1 : x1;
        const float ext   = isY ? rh : rw;
        const float coord = start + off * (ext / 7.f);

        if (coord > -1.f && coord < 128.f) {
            const float cl = fminf(fmaxf(coord, 0.f), 127.f);
            const int   i0 = (int)floorf(cl);
            const int   i1 = min(i0 + 1, HWD - 1);
            const float l  = cl - (float)i0;
            const float hi = 1.f - l;
            if (isY) {
                atomicAdd(&sa[i0], hi);
                atomicAdd(&sa[i1], l);
                atomicMin(&rlo_s, i0);
                atomicMax(&rhi_s, i1);
            } else {
                const float inv = 1.f / 196.f;  // fold in the mean
                atomicAdd(&sb[i0], hi * inv);
                atomicAdd(&sb[i1], l * inv);
                atomicMin(&clo_s, i0);
                atomicMax(&chi_s, i1);
            }
        }
    }
    __syncwarp();

    for (int i = lane; i < 128; i += 32) g_a[roi * 128 + i] = sa[i];
    for (int i = lane; i < 192; i += 32) g_b[roi * 192 + i] = sb[i];
    for (int i = lane; i < C_CH; i += 32) out[(size_t)roi * C_CH + i] = 0.f;

    if (lane == 0) {
        out[(size_t)n_rois * C_CH + roi] = rois[roi * 6 + 1];   // gt
        int base8 = 0, nch8 = 0;
        if (rhi_s >= rlo_s && chi_s >= clo_s) {
            base8 = clo_s & ~7;
            nch8  = ((chi_s - base8) >> 3) + 1;
        }
        g_meta[roi] = make_int4((int)rois[roi * 6 + 0], rlo_s, rhi_s,
                                base8 | (nch8 << 8));
    }
}

// ---------------------------------------------------------------------------
// Main: HMMA, weight fragments shared across two channel halves.
// ---------------------------------------------------------------------------
__global__ __launch_bounds__(NTHREADS, 2)
void roi_mma_kernel(const float* __restrict__ feat,
                    float* __restrict__ out, int n_rois)
{
    extern __shared__ __align__(16) char smem_dyn[];
    __half* tile = (__half*)(smem_dyn + OFF_TILE);
    __half* sb   = (__half*)(smem_dyn + OFF_SB);
    __half* sa   = (__half*)(smem_dyn + OFF_SA);
    float*  acc  = (float*)(smem_dyn + OFF_ACC);
    unsigned short* list_sh = (unsigned short*)(smem_dyn + OFF_LIST);
    int* cnt_sh = (int*)(smem_dyn + OFF_CNT);

    const int tid = threadIdx.x;
    const int rs0 = blockIdx.x * RS;
    const int cb0 = blockIdx.y * CB;
    const int bi  = blockIdx.z;

    if (tid == 0) *cnt_sh = 0;
    for (int i = tid; i < PASS * CB; i += NTHREADS) acc[i] = 0.f;

    // Stage the 16ch x 16row x 128col tile as fp16 (coalesced).
    const float* fsrc = feat + ((size_t)bi * C_CH + cb0) * (HWD * HWD)
                             + (size_t)rs0 * HWD;
    #pragma unroll
    for (int k = 0; k < 32; ++k) {
        const int idx = tid + k * NTHREADS;       // 0..8191 float4 slots
        const int ch  = idx >> 9;
        const int r   = (idx >> 5) & 15;
        const int c4  = idx & 31;
        const float4 v = *(const float4*)(fsrc + (size_t)ch * (HWD * HWD)
                                               + r * HWD + c4 * 4);
        __half2* dst = (__half2*)&tile[ch * SLAB_H + r * HWD + c4 * 4];
        dst[0] = __floats2half2_rn(v.x, v.y);
        dst[1] = __floats2half2_rn(v.z, v.w);
    }

    // List ROIs intersecting this (batch, strip).
    for (int t = tid; t < n_rois; t += NTHREADS) {
        const int4 m = g_meta[t];
        if (m.x == bi && (m.w >> 8) > 0 && m.y <= rs0 + RS - 1 && m.z >= rs0) {
            const int p = atomicAdd(cnt_sh, 1);
            if (p < MAXL) list_sh[p] = (unsigned short)t;
        }
    }
    __syncthreads();
    const int n = min(*cnt_sh, MAXL);

    const int warp = tid >> 5;
    const int lane = tid & 31;
    const int g  = lane >> 2;            // 0..7
    const int t2 = (lane & 3) * 2;       // 0,2,4,6

    for (int p0 = 0; p0 < n; p0 += PASS) {
        const int npass = min(PASS, n - p0);

        // Zero sa/sb (padded rois contribute 0), then fill listed rois.
        for (int i = tid; i < PASS * SB_STR / 2; i += NTHREADS)
            ((uint32_t*)sb)[i] = 0u;
        for (int i = tid; i < PASS * SA_STR / 2; i += NTHREADS)
            ((uint32_t*)sa)[i] = 0u;
        __syncthreads();
        for (int i = tid; i < npass * HWD; i += NTHREADS) {
            const int li = i >> 7, c = i & 127;
            const int roi = list_sh[p0 + li];
            sb[li * SB_STR + c] = __float2half_rn(g_b[roi * 192 + c]);
        }
        for (int i = tid; i < npass * RS; i += NTHREADS) {
            const int li = i >> 4, r = i & 15;
            const int roi = list_sh[p0 + li];
            sa[li * SA_STR + r] = __float2half_rn(g_a[roi * 128 + rs0 + r]);
        }
        __syncthreads();

        // This warp covers rows {2*warp, 2*warp+1} x 8 column windows.
        float d0[3][2] = {}, d1[3][2] = {}, d2[3][2] = {}, d3[3][2] = {};
        #pragma unroll 2
        for (int s = 0; s < 16; ++s) {
            const int r  = 2 * warp + (s >> 3);
            const int c0 = (s & 7) * 16;
            const int tb0 = g * SLAB_H + r * HWD + c0 + t2;
            const int tb1 = (g + 8) * SLAB_H + r * HWD + c0 + t2;
            const uint32_t bA0 = *(const uint32_t*)&tile[tb0];
            const uint32_t bA1 = *(const uint32_t*)&tile[tb0 + 8];
            const uint32_t bB0 = *(const uint32_t*)&tile[tb1];
            const uint32_t bB1 = *(const uint32_t*)&tile[tb1 + 8];
            #pragma unroll
            for (int G = 0; G < 3; ++G) {
                const int ra = G * 16 + g;
                const int rb = ra + 8;
                const __half2 aA = __half2half2(sa[ra * SA_STR + r]);
                const __half2 aB = __half2half2(sa[rb * SA_STR + r]);
                __half2 wa0 = __hmul2(aA, *(const __half2*)&sb[ra * SB_STR + c0 + t2]);
                __half2 wa1 = __hmul2(aB, *(const __half2*)&sb[rb * SB_STR + c0 + t2]);
                __half2 wa2 = __hmul2(aA, *(const __half2*)&sb[ra * SB_STR + c0 + t2 + 8]);
                __half2 wa3 = __hmul2(aB, *(const __half2*)&sb[rb * SB_STR + c0 + t2 + 8]);
                const uint32_t ua0 = *(const uint32_t*)&wa0;
                const uint32_t ua1 = *(const uint32_t*)&wa1;
                const uint32_t ua2 = *(const uint32_t*)&wa2;
                const uint32_t ua3 = *(const uint32_t*)&wa3;
                asm volatile(
                    "mma.sync.aligned.m16n8k16.row.col.f32.f16.f16.f32 "
                    "{%0,%1,%2,%3}, {%4,%5,%6,%7}, {%8,%9}, {%0,%1,%2,%3};"
                    : "+f"(d0[G][0]), "+f"(d1[G][0]), "+f"(d2[G][0]), "+f"(d3[G][0])
                    : "r"(ua0), "r"(ua1), "r"(ua2), "r"(ua3),
                      "r"(bA0), "r"(bA1));
                asm volatile(
                    "mma.sync.aligned.m16n8k16.row.col.f32.f16.f16.f32 "
                    "{%0,%1,%2,%3}, {%4,%5,%6,%7}, {%8,%9}, {%0,%1,%2,%3};"
                    : "+f"(d0[G][1]), "+f"(d1[G][1]), "+f"(d2[G][1]), "+f"(d3[G][1])
                    : "r"(ua0), "r"(ua1), "r"(ua2), "r"(ua3),
                      "r"(bB0), "r"(bB1));
            }
        }

        // Accumulate warp partials into the shared ROI x channel matrix.
        #pragma unroll
        for (int G = 0; G < 3; ++G) {
            #pragma unroll
            for (int h = 0; h < 2; ++h) {
                const int chb = h * 8 + t2;
                atomicAdd(&acc[(G * 16 + g) * CB + chb],         d0[G][h]);
                atomicAdd(&acc[(G * 16 + g) * CB + chb + 1],     d1[G][h]);
                atomicAdd(&acc[(G * 16 + g + 8) * CB + chb],     d2[G][h]);
                atomicAdd(&acc[(G * 16 + g + 8) * CB + chb + 1], d3[G][h]);
            }
        }
        __syncthreads();

        // Flush to global and re-zero for the (rare) next pass.
        for (int i = tid; i < npass * CB; i += NTHREADS) {
            const int li = i >> 4, ch = i & 15;
            const int roi = list_sh[p0 + li];
            atomicAdd(out + (size_t)roi * C_CH + cb0 + ch, acc[li * CB + ch]);
            acc[li * CB + ch] = 0.f;
        }
        __syncthreads();
    }
}

extern "C" void kernel_launch(void* const* d_in, const int* in_sizes, int n_in,
                              void* d_out, int out_size)
{
    const float* feat = (const float*)d_in[0];   // (4, 256, 128, 128) fp32
    const float* rois = (const float*)d_in[1];   // (N, 6) fp32
    float* out = (float*)d_out;

    const int n_rois = in_sizes[1] / 6;          // 512
    (void)n_in; (void)out_size;

    cudaFuncSetAttribute(roi_mma_kernel,
                         cudaFuncAttributeMaxDynamicSharedMemorySize,
                         SMEM_TOTAL);

    roi_setup_kernel<<<n_rois, 32>>>(rois, out, n_rois);

    dim3 grid(HWD / RS, C_CH / CB, 4);           // (8, 16, 4)
    roi_mma_kernel<<<grid, NTHREADS, SMEM_TOTAL>>>(feat, out, n_rois);
}

// round 17
// speedup vs baseline: 1.2619x; 1.2619x over previous
#include <cuda_runtime.h>
#include <cuda_fp16.h>
#include <cstdint>

// ROIAlign(7x7, sr=2) + global avg pool via separable weights + HMMA.
//
// out[roi,ch] = sum_{r,c} a[roi][r]*b[roi][c] * F[bi,ch,r,c]
// Per (batch, 8-row strip, 16-channel block):
//   D[16ch x 8roi] per mma, A = F (pure LDS from fp16 tile, reused across
//   all 6 roi-groups), B = W[k][roi] = a[roi][r]*b[roi][c] built with just
//   2 LDS + 2 HMUL2 per mma. Warp w owns row r=w (8 warps = 8 rows); each
//   warp runs 8 col-windows x 6 groups = 48 mmas/pass. Cross-warp partials
//   are summed via conflict-free smem staging, then one atomicAdd flush.

#define C_CH   256
#define HWD    128
#define RS     8
#define CB     16
#define NTHREADS 256
#define SLAB_H  1034             // halves per channel slab (517 words == 5 mod 32)
#define SB_STR  136              // sb row stride in halves
#define PASS    48               // rois per pass (6 groups of 8)
#define NGRP    6
#define MAXL    128              // max rois per (batch, strip)

// dynamic smem layout (bytes)
#define OFF_TILE 0
#define OFF_SB   (OFF_TILE + CB * SLAB_H * 2)        // 33088
#define OFF_SA   (OFF_SB + PASS * SB_STR * 2)        // +13056 = 46144
#define OFF_RED  (OFF_SA + PASS * RS * 2)            // +768   = 46912
#define OFF_LIST (OFF_RED + 24 * 256 * 4)            // +24576 = 71488
#define OFF_CNT  (OFF_LIST + MAXL * 2)               // +256   = 71744
#define SMEM_TOTAL (OFF_CNT + 16)                    // 71760

__device__ __align__(16) float g_a[512 * 128];
__device__ __align__(16) float g_b[512 * 192];
__device__ int4 g_meta[512];     // {bi, rlo, rhi, nch8<<8 | base8}

// ---------------------------------------------------------------------------
// Setup: one 32-thread block per ROI (marginals + meta + out init).
// ---------------------------------------------------------------------------
__global__ void roi_setup_kernel(const float* __restrict__ rois,
                                 float* __restrict__ out, int n_rois)
{
    __shared__ float sa[128];
    __shared__ float sb[192];
    __shared__ int rlo_s, rhi_s, clo_s, chi_s;

    const int roi  = blockIdx.x;
    const int lane = threadIdx.x;

    if (lane == 0) { rlo_s = 1 << 30; rhi_s = -1; clo_s = 1 << 30; chi_s = -1; }
    for (int i = lane; i < 192; i += 32) { if (i < 128) sa[i] = 0.f; sb[i] = 0.f; }
    __syncwarp();

    const bool isY = (lane < 14);
    const bool isX = (lane >= 16 && lane < 30);
    if (isY || isX) {
        const int s = isY ? lane : lane - 16;
        const float cx = rois[roi * 6 + 2];
        const float cy = rois[roi * 6 + 3];
        const float w  = rois[roi * 6 + 4];
        const float h  = rois[roi * 6 + 5];
        // Reference rounds the scaled corners through fp16.
        const float x1 = __half2float(__float2half_rn((cx - 0.5f * w) * 128.f));
        const float x2 = __half2float(__float2half_rn((cx + 0.5f * w) * 128.f));
        const float y1 = __half2float(__float2half_rn((cy - 0.5f * h) * 128.f));
        const float y2 = __half2float(__float2half_rn((cy + 0.5f * h) * 128.f));
        const float rw = fmaxf(x2 - x1, 1.f);
        const float rh = fmaxf(y2 - y1, 1.f);

        const float off   = 0.25f + 0.5f * (float)s;
        const float start = isY ? y1 : x1;
        const float ext   = isY ? rh : rw;
        const float coord = start + off * (ext / 7.f);

        if (coord > -1.f && coord < 128.f) {
            const float cl = fminf(fmaxf(coord, 0.f), 127.f);
            const int   i0 = (int)floorf(cl);
            const int   i1 = min(i0 + 1, HWD - 1);
            const float l  = cl - (float)i0;
            const float hi = 1.f - l;
            if (isY) {
                atomicAdd(&sa[i0], hi);
                atomicAdd(&sa[i1], l);
                atomicMin(&rlo_s, i0);
                atomicMax(&rhi_s, i1);
            } else {
                const float inv = 1.f / 196.f;  // fold in the mean
                atomicAdd(&sb[i0], hi * inv);
                atomicAdd(&sb[i1], l * inv);
                atomicMin(&clo_s, i0);
                atomicMax(&chi_s, i1);
            }
        }
    }
    __syncwarp();

    for (int i = lane; i < 128; i += 32) g_a[roi * 128 + i] = sa[i];
    for (int i = lane; i < 192; i += 32) g_b[roi * 192 + i] = sb[i];
    for (int i = lane; i < C_CH; i += 32) out[(size_t)roi * C_CH + i] = 0.f;

    if (lane == 0) {
        out[(size_t)n_rois * C_CH + roi] = rois[roi * 6 + 1];   // gt
        int base8 = 0, nch8 = 0;
        if (rhi_s >= rlo_s && chi_s >= clo_s) {
            base8 = clo_s & ~7;
            nch8  = ((chi_s - base8) >> 3) + 1;
        }
        g_meta[roi] = make_int4((int)rois[roi * 6 + 0], rlo_s, rhi_s,
                                base8 | (nch8 << 8));
    }
}

// ---------------------------------------------------------------------------
// Main: HMMA with features on the A (reused) side.
// ---------------------------------------------------------------------------
__global__ __launch_bounds__(NTHREADS, 3)
void roi_mma_kernel(const float* __restrict__ feat,
                    float* __restrict__ out, int n_rois)
{
    extern __shared__ __align__(16) char smem_dyn[];
    __half* tile = (__half*)(smem_dyn + OFF_TILE);
    __half* sb   = (__half*)(smem_dyn + OFF_SB);
    __half* sa   = (__half*)(smem_dyn + OFF_SA);
    float*  red  = (float*)(smem_dyn + OFF_RED);
    unsigned short* list_sh = (unsigned short*)(smem_dyn + OFF_LIST);
    int* cnt_sh = (int*)(smem_dyn + OFF_CNT);

    const int tid = threadIdx.x;
    const int rs0 = blockIdx.x * RS;
    const int cb0 = blockIdx.y * CB;
    const int bi  = blockIdx.z;

    if (tid == 0) *cnt_sh = 0;

    // Stage the 16ch x 8row x 128col tile as fp16 (coalesced).
    const float* fsrc = feat + ((size_t)bi * C_CH + cb0) * (HWD * HWD)
                             + (size_t)rs0 * HWD;
    #pragma unroll
    for (int k = 0; k < 16; ++k) {
        const int idx = tid + k * NTHREADS;       // 0..4095 float4 slots
        const int ch  = idx >> 8;                 // 256 slots per channel
        const int r   = (idx >> 5) & 7;
        const int c4  = idx & 31;
        const float4 v = *(const float4*)(fsrc + (size_t)ch * (HWD * HWD)
                                               + r * HWD + c4 * 4);
        __half2* dst = (__half2*)&tile[ch * SLAB_H + r * HWD + c4 * 4];
        dst[0] = __floats2half2_rn(v.x, v.y);
        dst[1] = __floats2half2_rn(v.z, v.w);
    }

    // List ROIs intersecting this (batch, strip).
    for (int t = tid; t < n_rois; t += NTHREADS) {
        const int4 m = g_meta[t];
        if (m.x == bi && (m.w >> 8) > 0 && m.y <= rs0 + RS - 1 && m.z >= rs0) {
            const int p = atomicAdd(cnt_sh, 1);
            if (p < MAXL) list_sh[p] = (unsigned short)t;
        }
    }
    __syncthreads();
    const int n = min(*cnt_sh, MAXL);

    const int warp = tid >> 5;          // = feature row r within the strip
    const int lane = tid & 31;
    const int g  = lane >> 2;            // 0..7
    const int t2 = (lane & 3) * 2;       // 0,2,4,6

    for (int p0 = 0; p0 < n; p0 += PASS) {
        const int npass = min(PASS, n - p0);

        // Zero weight arrays (padded rois contribute 0), then fill.
        for (int i = tid; i < PASS * SB_STR / 2; i += NTHREADS)
            ((uint32_t*)sb)[i] = 0u;
        for (int i = tid; i < PASS * RS / 2; i += NTHREADS)
            ((uint32_t*)sa)[i] = 0u;
        __syncthreads();
        for (int i = tid; i < npass * HWD; i += NTHREADS) {
            const int li = i >> 7, c = i & 127;
            const int roi = list_sh[p0 + li];
            sb[li * SB_STR + c] = __float2half_rn(g_b[roi * 192 + c]);
        }
        for (int i = tid; i < npass * RS; i += NTHREADS) {
            const int li = i >> 3, r = i & 7;
            const int roi = list_sh[p0 + li];
            sa[li * RS + r] = __float2half_rn(g_a[roi * 128 + rs0 + r]);
        }
        __syncthreads();

        // Hoist per-group row weights: lane's B-col roi is (G*8 + g).
        __half2 saG[NGRP];
        #pragma unroll
        for (int G = 0; G < NGRP; ++G)
            saG[G] = __half2half2(sa[(G * 8 + g) * RS + warp]);

        float d0[NGRP] = {}, d1[NGRP] = {}, d2[NGRP] = {}, d3[NGRP] = {};
        #pragma unroll 2
        for (int cw = 0; cw < 8; ++cw) {
            const int c0 = cw * 16;
            // A fragments (features), reused across all 6 groups.
            const uint32_t a0 = *(const uint32_t*)&tile[g * SLAB_H + warp * HWD + c0 + t2];
            const uint32_t a1 = *(const uint32_t*)&tile[(g + 8) * SLAB_H + warp * HWD + c0 + t2];
            const uint32_t a2 = *(const uint32_t*)&tile[g * SLAB_H + warp * HWD + c0 + t2 + 8];
            const uint32_t a3 = *(const uint32_t*)&tile[(g + 8) * SLAB_H + warp * HWD + c0 + t2 + 8];
            #pragma unroll
            for (int G = 0; G < NGRP; ++G) {
                const __half2 wb0 = __hmul2(saG[G],
                    *(const __half2*)&sb[(G * 8 + g) * SB_STR + c0 + t2]);
                const __half2 wb1 = __hmul2(saG[G],
                    *(const __half2*)&sb[(G * 8 + g) * SB_STR + c0 + t2 + 8]);
                const uint32_t ub0 = *(const uint32_t*)&wb0;
                const uint32_t ub1 = *(const uint32_t*)&wb1;
                asm volatile(
                    "mma.sync.aligned.m16n8k16.row.col.f32.f16.f16.f32 "
                    "{%0,%1,%2,%3}, {%4,%5,%6,%7}, {%8,%9}, {%0,%1,%2,%3};"
                    : "+f"(d0[G]), "+f"(d1[G]), "+f"(d2[G]), "+f"(d3[G])
                    : "r"(a0), "r"(a1), "r"(a2), "r"(a3),
                      "r"(ub0), "r"(ub1));
            }
        }

        // Stage warp partials (conflict-free), then cross-warp sum + flush.
        #pragma unroll
        for (int G = 0; G < NGRP; ++G) {
            red[(G * 4 + 0) * 256 + warp * 32 + lane] = d0[G];
            red[(G * 4 + 1) * 256 + warp * 32 + lane] = d1[G];
            red[(G * 4 + 2) * 256 + warp * 32 + lane] = d2[G];
            red[(G * 4 + 3) * 256 + warp * 32 + lane] = d3[G];
        }
        __syncthreads();

        for (int o = tid; o < 24 * 32; o += NTHREADS) {
            const int j  = o >> 5;       // 0..23  (G*4 + di)
            const int lo = o & 31;
            float v = 0.f;
            #pragma unroll
            for (int w = 0; w < 8; ++w)
                v += red[j * 256 + w * 32 + lo];
            const int G  = j >> 2;
            const int di = j & 3;
            const int go = lo >> 2;
            const int tp = lo & 3;
            const int ridx = G * 8 + 2 * tp + (di & 1);
            if (ridx < npass) {
                const int roi = list_sh[p0 + ridx];
                const int ch  = cb0 + go + ((di >> 1) << 3);
                atomicAdd(out + (size_t)roi * C_CH + ch, v);
            }
        }
        __syncthreads();
    }
}

extern "C" void kernel_launch(void* const* d_in, const int* in_sizes, int n_in,
                              void* d_out, int out_size)
{
    const float* feat = (const float*)d_in[0];   // (4, 256, 128, 128) fp32
    const float* rois = (const float*)d_in[1];   // (N, 6) fp32
    float* out = (float*)d_out;

    const int n_rois = in_sizes[1] / 6;          // 512
    (void)n_in; (void)out_size;

    cudaFuncSetAttribute(roi_mma_kernel,
                         cudaFuncAttributeMaxDynamicSharedMemorySize,
                         SMEM_TOTAL);

    roi_setup_kernel<<<n_rois, 32>>>(rois, out, n_rois);

    dim3 grid(HWD / RS, C_CH / CB, 4);           // (16, 16, 4)
    roi_mma_kernel<<<grid, NTHREADS, SMEM_TOTAL>>>(feat, out, n_rois);
}